// round 6
// baseline (speedup 1.0000x reference)
#include <cuda_runtime.h>
#include <math.h>
#include <stdint.h>

#define NB   4
#define TT   1024
#define HH   8
#define DD   64
#define DMOD 512
#define DFFV 1024
#define NLAY 6
#define ROWS (NB * TT)   // 4096
#define NH   (NB * HH)   // 32

// q pre-scaled by (1/sqrt(D)) * log2(e): softmax in exp2 domain
#define QSCALE (0.125f * 1.4426950408889634f)

// ---------------- scratch (static device globals; no allocation) -------------
__device__ float g_h  [ROWS * DMOD];
__device__ float g_att[ROWS * DMOD];
__device__ float g_ff1[ROWS * DFFV];
__device__ float g_ff2[ROWS * DMOD];
__device__ float g_q  [NH * TT * DD];
__device__ float g_k  [NH * TT * DD];
__device__ float g_v  [NH * TT * DD];

// ---------------- embedding + positional encoding ----------------------------
__global__ void embed_kernel(const int* __restrict__ x, const float* __restrict__ emb)
{
    int row = blockIdx.x;
    int t   = row & (TT - 1);
    int tok = x[row];
    const float* e = emb + (size_t)tok * DMOD;
    for (int i = threadIdx.x; i < DMOD; i += blockDim.x) {
        double expo = -2.0 * (double)(i >> 1) / (double)DMOD;
        double ang  = (double)t * pow(10000.0, expo);
        float  p    = (i & 1) ? (float)cos(ang) : (float)sin(ang);
        g_h[(size_t)row * DMOD + i] = e[i] * 22.62741699796952f + p;  // sqrt(512)
    }
}

// ---------------- common PTX helpers -------------------------------------------
__device__ __forceinline__ uint32_t f2tf(float f)
{
    uint32_t r;
    asm("cvt.rna.tf32.f32 %0, %1;" : "=r"(r) : "f"(f));
    return r;
}
__device__ __forceinline__ void tfsplit(float x, uint32_t& big, uint32_t& small)
{
    big   = f2tf(x);
    small = f2tf(x - __uint_as_float(big));
}
__device__ __forceinline__ void mma_tf32(float* c, const uint32_t* a, uint32_t b0, uint32_t b1)
{
    asm volatile(
        "mma.sync.aligned.m16n8k8.row.col.f32.tf32.tf32.f32 "
        "{%0,%1,%2,%3}, {%4,%5,%6,%7}, {%8,%9}, {%0,%1,%2,%3};"
        : "+f"(c[0]), "+f"(c[1]), "+f"(c[2]), "+f"(c[3])
        : "r"(a[0]), "r"(a[1]), "r"(a[2]), "r"(a[3]), "r"(b0), "r"(b1));
}
__device__ __forceinline__ void cp_async16(uint32_t saddr, const void* gaddr)
{
    asm volatile("cp.async.cg.shared.global [%0], [%1], 16;" :: "r"(saddr), "l"(gaddr));
}
__device__ __forceinline__ void cp_commit() { asm volatile("cp.async.commit_group;"); }
template<int N> __device__ __forceinline__ void cp_wait() {
    asm volatile("cp.async.wait_group %0;" :: "n"(N));
}
__device__ __forceinline__ float ex2(float x)
{
    float r;
    asm("ex2.approx.ftz.f32 %0, %1;" : "=f"(r) : "f"(x));
    return r;
}

// scatter one qkv-gemm output element into g_q / g_k / g_v
__device__ __forceinline__ void store_qkv(int row, int col, float val)
{
    int h = col / 192;
    int r = col - h * 192;
    int d = r / 3;
    int j = r - d * 3;
    int n = row >> 10, t = row & (TT - 1);
    size_t dst = ((size_t)(n * HH + h) * TT + t) * DD + d;
    if (j == 0)      g_q[dst] = val * QSCALE;
    else if (j == 1) g_k[dst] = val;
    else             g_v[dst] = val;
}

// ---------------- TF32 GEMM, 3-stage cp.async pipeline -------------------------
// C[M,N] = A[M,K] @ B[K,N] + bias.  MODE: 0 plain, 1 ReLU, 2 scatter to q/k/v.
#define LDA 20u
#define LDB 136u
#define STG 3

template<int MODE>
__global__ __launch_bounds__(256)
void gemm_tf32(const float* __restrict__ A, const float* __restrict__ B,
               const float* __restrict__ bias, float* __restrict__ C,
               int M, int N, int K)
{
    __shared__ float As[STG][128 * LDA];
    __shared__ float Bs[STG][16 * LDB];

    const int tid  = threadIdx.x;
    const int bm   = blockIdx.y * 128;
    const int bn   = blockIdx.x * 128;

    const int am = tid >> 1, ak = (tid & 1) * 8;
    const int bk = tid >> 4, bcol = (tid & 15) * 8;

    const uint32_t sA = (uint32_t)__cvta_generic_to_shared(&As[0][0]);
    const uint32_t sB = (uint32_t)__cvta_generic_to_shared(&Bs[0][0]);

    const int warp = tid >> 5, lane = tid & 31;
    const int gid  = lane >> 2, tig = lane & 3;
    const int wm   = (warp & 3) * 32;
    const int wn   = (warp >> 2) * 64;

    float c[2][8][4];
#pragma unroll
    for (int mt = 0; mt < 2; ++mt)
#pragma unroll
        for (int nt = 0; nt < 8; ++nt)
#pragma unroll
            for (int j = 0; j < 4; ++j) c[mt][nt][j] = 0.f;

    const int nIter = K >> 4;

    auto issue = [&](int t) {
        const int buf = t % STG;
        const float* Ap = A + (size_t)(bm + am) * K + t * 16 + ak;
        const float* Bp = B + (size_t)(t * 16 + bk) * N + bn + bcol;
        uint32_t sa = sA + (buf * 128 * LDA + am * LDA + ak) * 4;
        uint32_t sb = sB + (buf * 16 * LDB + bk * LDB + bcol) * 4;
        cp_async16(sa,      Ap);
        cp_async16(sa + 16, Ap + 4);
        cp_async16(sb,      Bp);
        cp_async16(sb + 16, Bp + 4);
        cp_commit();
    };

    issue(0);
    if (nIter > 1) issue(1);

    for (int it = 0; it < nIter; ++it) {
        // make buffer `it` visible to all threads
        if (it + 1 < nIter) cp_wait<1>(); else cp_wait<0>();
        __syncthreads();

        // prefetch 2 ahead (safe: previous compute on this buffer finished
        // before the barrier above)
        if (it + 2 < nIter) issue(it + 2);

        const float* Ac = As[it % STG];
        const float* Bc = Bs[it % STG];
#pragma unroll
        for (int ks = 0; ks < 2; ++ks) {
            const int kb = ks * 8;
            uint32_t a[2][4], b[8][2];
#pragma unroll
            for (int mt = 0; mt < 2; ++mt) {
                const int r = wm + mt * 16 + gid;
                a[mt][0] = f2tf(Ac[(uint32_t)r * LDA + kb + tig]);
                a[mt][1] = f2tf(Ac[(uint32_t)(r + 8) * LDA + kb + tig]);
                a[mt][2] = f2tf(Ac[(uint32_t)r * LDA + kb + tig + 4]);
                a[mt][3] = f2tf(Ac[(uint32_t)(r + 8) * LDA + kb + tig + 4]);
            }
#pragma unroll
            for (int nt = 0; nt < 8; ++nt) {
                const int col = wn + nt * 8 + gid;
                b[nt][0] = f2tf(Bc[(uint32_t)(kb + tig) * LDB + col]);
                b[nt][1] = f2tf(Bc[(uint32_t)(kb + tig + 4) * LDB + col]);
            }
#pragma unroll
            for (int mt = 0; mt < 2; ++mt)
#pragma unroll
                for (int nt = 0; nt < 8; ++nt)
                    mma_tf32(c[mt][nt], a[mt], b[nt][0], b[nt][1]);
        }
    }

    // ---- epilogue ----
#pragma unroll
    for (int mt = 0; mt < 2; ++mt) {
        const int row0 = bm + wm + mt * 16 + gid;
#pragma unroll
        for (int nt = 0; nt < 8; ++nt) {
            const int coln = bn + wn + nt * 8 + 2 * tig;
            const float2 bv = *(const float2*)(bias + coln);
            float2 v0, v1;
            v0.x = c[mt][nt][0] + bv.x; v0.y = c[mt][nt][1] + bv.y;
            v1.x = c[mt][nt][2] + bv.x; v1.y = c[mt][nt][3] + bv.y;
            if (MODE == 1) {
                v0.x = fmaxf(v0.x, 0.f); v0.y = fmaxf(v0.y, 0.f);
                v1.x = fmaxf(v1.x, 0.f); v1.y = fmaxf(v1.y, 0.f);
            }
            if (MODE == 2) {
                store_qkv(row0,     coln,     v0.x);
                store_qkv(row0,     coln + 1, v0.y);
                store_qkv(row0 + 8, coln,     v1.x);
                store_qkv(row0 + 8, coln + 1, v1.y);
            } else {
                *(float2*)(C + (size_t)row0 * N + coln)       = v0;
                *(float2*)(C + (size_t)(row0 + 8) * N + coln) = v1;
            }
        }
    }
}

// ---------------- FlashAttention-2, compensated tf32 (unchanged from R5) -------
#define LDK 68
#define LDV 72
#define LDP 76
#define OFF_K0 0
#define OFF_K1 (64 * LDK)
#define OFF_V0 (2 * 64 * LDK)
#define OFF_V1 (OFF_V0 + 64 * LDV)
#define OFF_P  (OFF_V0 + 2 * 64 * LDV)
#define ATTN_SMEM_FLOATS (OFF_P + 4 * 16 * LDP)
#define ATTN_SMEM_BYTES  (ATTN_SMEM_FLOATS * 4)   // 91136

__global__ __launch_bounds__(128)
void attn_mma_kernel()
{
    extern __shared__ float sm[];

    const int tid  = threadIdx.x;
    const int warp = tid >> 5, lane = tid & 31;
    const int gid  = lane >> 2, tig = lane & 3;
    const int qt   = gridDim.x - 1 - blockIdx.x;   // heavy tiles first
    const int nh   = blockIdx.y;
    const int row0 = qt * 64 + warp * 16;

    const float* kb = g_k + (size_t)nh * TT * DD;
    const float* vb = g_v + (size_t)nh * TT * DD;

    const uint32_t sbase = (uint32_t)__cvta_generic_to_shared(sm);

    uint32_t qfb[8][4], qfs[8][4];
    {
        const float* qp = g_q + ((size_t)nh * TT + row0) * DD;
#pragma unroll
        for (int kt = 0; kt < 8; ++kt) {
            tfsplit(qp[gid * DD + kt * 8 + tig],           qfb[kt][0], qfs[kt][0]);
            tfsplit(qp[(gid + 8) * DD + kt * 8 + tig],     qfb[kt][1], qfs[kt][1]);
            tfsplit(qp[gid * DD + kt * 8 + tig + 4],       qfb[kt][2], qfs[kt][2]);
            tfsplit(qp[(gid + 8) * DD + kt * 8 + tig + 4], qfb[kt][3], qfs[kt][3]);
        }
    }

    float o[8][4];
#pragma unroll
    for (int nt = 0; nt < 8; ++nt)
#pragma unroll
        for (int j = 0; j < 4; ++j) o[nt][j] = 0.f;
    float m0 = -INFINITY, m1 = -INFINITY, l0 = 0.f, l1 = 0.f;

    const int ntiles = qt + 1;

    auto prefetch = [&](int t) {
        const size_t gb = (size_t)t * 64 * DD;
        const uint32_t kOff = (t & 1) ? OFF_K1 : OFF_K0;
        const uint32_t vOff = (t & 1) ? OFF_V1 : OFF_V0;
#pragma unroll
        for (int i = 0; i < 8; ++i) {
            int idx = i * 128 + tid;
            int r   = idx >> 4;
            int c4  = (idx & 15) * 4;
            cp_async16(sbase + (kOff + r * LDK + c4) * 4, kb + gb + r * DD + c4);
            cp_async16(sbase + (vOff + r * LDV + c4) * 4, vb + gb + r * DD + c4);
        }
    };

    prefetch(0);
    cp_commit();

    float* Pw = sm + OFF_P + warp * 16 * LDP;

#pragma unroll 1
    for (int kt_i = 0; kt_i < ntiles; ++kt_i) {
        if (kt_i + 1 < ntiles) {
            prefetch(kt_i + 1);
            cp_commit();
            cp_wait<1>();
        } else {
            cp_wait<0>();
        }
        __syncthreads();

        const float* Kt = sm + ((kt_i & 1) ? OFF_K1 : OFF_K0);
        const float* Vt = sm + ((kt_i & 1) ? OFF_V1 : OFF_V0);

        float cs[8][4];
#pragma unroll
        for (int nt = 0; nt < 8; ++nt) {
#pragma unroll
            for (int j = 0; j < 4; ++j) cs[nt][j] = 0.f;
#pragma unroll
            for (int dk = 0; dk < 8; ++dk) {
                uint32_t bb0, bs0, bb1, bs1;
                tfsplit(Kt[(nt * 8 + gid) * LDK + dk * 8 + tig],     bb0, bs0);
                tfsplit(Kt[(nt * 8 + gid) * LDK + dk * 8 + tig + 4], bb1, bs1);
                mma_tf32(cs[nt], qfb[dk], bb0, bb1);
                mma_tf32(cs[nt], qfb[dk], bs0, bs1);
                mma_tf32(cs[nt], qfs[dk], bb0, bb1);
            }
        }

        if (kt_i == qt) {
            const int rl0 = warp * 16 + gid;
            const int rl1 = rl0 + 8;
#pragma unroll
            for (int nt = 0; nt < 8; ++nt) {
                int j = nt * 8 + 2 * tig;
                if (j     > rl0) cs[nt][0] = -INFINITY;
                if (j + 1 > rl0) cs[nt][1] = -INFINITY;
                if (j     > rl1) cs[nt][2] = -INFINITY;
                if (j + 1 > rl1) cs[nt][3] = -INFINITY;
            }
        }

        float mx0 = -INFINITY, mx1 = -INFINITY;
#pragma unroll
        for (int nt = 0; nt < 8; ++nt) {
            mx0 = fmaxf(mx0, fmaxf(cs[nt][0], cs[nt][1]));
            mx1 = fmaxf(mx1, fmaxf(cs[nt][2], cs[nt][3]));
        }
        mx0 = fmaxf(mx0, __shfl_xor_sync(0xffffffffu, mx0, 1));
        mx0 = fmaxf(mx0, __shfl_xor_sync(0xffffffffu, mx0, 2));
        mx1 = fmaxf(mx1, __shfl_xor_sync(0xffffffffu, mx1, 1));
        mx1 = fmaxf(mx1, __shfl_xor_sync(0xffffffffu, mx1, 2));

        const float mn0 = fmaxf(m0, mx0);
        const float mn1 = fmaxf(m1, mx1);
        const float cor0 = ex2(m0 - mn0);
        const float cor1 = ex2(m1 - mn1);
        l0 *= cor0; l1 *= cor1;
#pragma unroll
        for (int nt = 0; nt < 8; ++nt) {
            o[nt][0] *= cor0; o[nt][1] *= cor0;
            o[nt][2] *= cor1; o[nt][3] *= cor1;
        }

        float rs0 = 0.f, rs1 = 0.f;
#pragma unroll
        for (int nt = 0; nt < 8; ++nt) {
            float p0 = ex2(cs[nt][0] - mn0);
            float p1 = ex2(cs[nt][1] - mn0);
            float p2 = ex2(cs[nt][2] - mn1);
            float p3 = ex2(cs[nt][3] - mn1);
            rs0 += p0 + p1; rs1 += p2 + p3;
            int col = nt * 8 + 2 * tig;
            *(float2*)(Pw + gid * LDP + col)       = make_float2(p0, p1);
            *(float2*)(Pw + (gid + 8) * LDP + col) = make_float2(p2, p3);
        }
        rs0 += __shfl_xor_sync(0xffffffffu, rs0, 1);
        rs0 += __shfl_xor_sync(0xffffffffu, rs0, 2);
        rs1 += __shfl_xor_sync(0xffffffffu, rs1, 1);
        rs1 += __shfl_xor_sync(0xffffffffu, rs1, 2);
        l0 += rs0; l1 += rs1;
        m0 = mn0; m1 = mn1;

        __syncwarp();

#pragma unroll
        for (int kk = 0; kk < 8; ++kk) {
            uint32_t ab[4], as_[4];
            tfsplit(Pw[gid * LDP + kk * 8 + tig],           ab[0], as_[0]);
            tfsplit(Pw[(gid + 8) * LDP + kk * 8 + tig],     ab[1], as_[1]);
            tfsplit(Pw[gid * LDP + kk * 8 + tig + 4],       ab[2], as_[2]);
            tfsplit(Pw[(gid + 8) * LDP + kk * 8 + tig + 4], ab[3], as_[3]);
#pragma unroll
            for (int nt = 0; nt < 8; ++nt) {
                uint32_t bb0, bs0, bb1, bs1;
                tfsplit(Vt[(kk * 8 + tig) * LDV + nt * 8 + gid],     bb0, bs0);
                tfsplit(Vt[(kk * 8 + tig + 4) * LDV + nt * 8 + gid], bb1, bs1);
                mma_tf32(o[nt], ab,  bb0, bb1);
                mma_tf32(o[nt], ab,  bs0, bs1);
                mma_tf32(o[nt], as_, bb0, bb1);
            }
        }
    }

    const float i0 = 1.f / l0;
    const float i1 = 1.f / l1;
    const int n = nh >> 3, hh = nh & 7;
    const int rg0 = row0 + gid;
#pragma unroll
    for (int nt = 0; nt < 8; ++nt) {
        int col = hh * DD + nt * 8 + 2 * tig;
        *(float2*)(g_att + (size_t)(n * TT + rg0) * DMOD + col) =
            make_float2(o[nt][0] * i0, o[nt][1] * i0);
        *(float2*)(g_att + (size_t)(n * TT + rg0 + 8) * DMOD + col) =
            make_float2(o[nt][2] * i1, o[nt][3] * i1);
    }
}

// ---------------- fused residual add + LayerNorm ------------------------------
__global__ __launch_bounds__(256)
void add_ln_kernel(const float* __restrict__ a, const float* __restrict__ b,
                   const float* __restrict__ gamma, const float* __restrict__ beta,
                   float* __restrict__ out)
{
    int row = blockIdx.x;
    int tid = threadIdx.x;
    const float* ar = a + (size_t)row * DMOD;
    const float* br = b + (size_t)row * DMOD;

    float x0 = ar[tid]       + br[tid];
    float x1 = ar[tid + 256] + br[tid + 256];

    float sum = x0 + x1;
    float sq  = x0 * x0 + x1 * x1;
#pragma unroll
    for (int off = 16; off; off >>= 1) {
        sum += __shfl_xor_sync(0xffffffffu, sum, off);
        sq  += __shfl_xor_sync(0xffffffffu, sq,  off);
    }
    __shared__ float s1[8], s2[8];
    int wid = tid >> 5, lane = tid & 31;
    if (lane == 0) { s1[wid] = sum; s2[wid] = sq; }
    __syncthreads();
    float S = 0.f, Q = 0.f;
#pragma unroll
    for (int i = 0; i < 8; ++i) { S += s1[i]; Q += s2[i]; }

    float mean = S * (1.f / DMOD);
    float var  = Q * (1.f / DMOD) - mean * mean;
    float rstd = 1.f / sqrtf(var + 1e-3f);

    out[(size_t)row * DMOD + tid]       = gamma[tid]       * (x0 - mean) * rstd + beta[tid];
    out[(size_t)row * DMOD + tid + 256] = gamma[tid + 256] * (x1 - mean) * rstd + beta[tid + 256];
}

// ---------------- launch ------------------------------------------------------
extern "C" void kernel_launch(void* const* d_in, const int* in_sizes, int n_in,
                              void* d_out, int out_size)
{
    const int*   x     = (const int*)  d_in[0];
    const float* emb   = (const float*)d_in[1];
    const float* Wqkv  = (const float*)d_in[2];
    const float* bqkv  = (const float*)d_in[3];
    const float* Wff   = (const float*)d_in[4];
    const float* bff   = (const float*)d_in[5];
    const float* Wo    = (const float*)d_in[6];
    const float* bo    = (const float*)d_in[7];
    const float* g1    = (const float*)d_in[8];
    const float* beta1 = (const float*)d_in[9];
    const float* g2    = (const float*)d_in[10];
    const float* beta2 = (const float*)d_in[11];
    float* out = (float*)d_out;

    float *h, *att, *ff1, *ff2;
    cudaGetSymbolAddress((void**)&h,   g_h);
    cudaGetSymbolAddress((void**)&att, g_att);
    cudaGetSymbolAddress((void**)&ff1, g_ff1);
    cudaGetSymbolAddress((void**)&ff2, g_ff2);

    cudaFuncSetAttribute(attn_mma_kernel,
                         cudaFuncAttributeMaxDynamicSharedMemorySize, ATTN_SMEM_BYTES);

    embed_kernel<<<ROWS, 128>>>(x, emb);

    for (int l = 0; l < NLAY; ++l) {
        // QKV projection fused with head-split scatter
        gemm_tf32<2><<<dim3(1536 / 128, ROWS / 128), 256>>>(
            h, Wqkv + (size_t)l * DMOD * 3 * DMOD, bqkv + (size_t)l * 3 * DMOD,
            nullptr, ROWS, 3 * DMOD, DMOD);

        attn_mma_kernel<<<dim3(TT / 64, NH), 128, ATTN_SMEM_BYTES>>>();

        add_ln_kernel<<<ROWS, 256>>>(h, att, g1 + (size_t)l * DMOD, beta1 + (size_t)l * DMOD, h);

        gemm_tf32<1><<<dim3(DFFV / 128, ROWS / 128), 256>>>(
            h, Wff + (size_t)l * DMOD * DFFV, bff + (size_t)l * DFFV,
            ff1, ROWS, DFFV, DMOD);

        gemm_tf32<0><<<dim3(DMOD / 128, ROWS / 128), 256>>>(
            ff1, Wo + (size_t)l * DFFV * DMOD, bo + (size_t)l * DMOD,
            ff2, ROWS, DMOD, DFFV);

        add_ln_kernel<<<ROWS, 256>>>(h, ff2, g2 + (size_t)l * DMOD, beta2 + (size_t)l * DMOD,
                                     (l == NLAY - 1) ? out : h);
    }
}

// round 7
// speedup vs baseline: 1.1238x; 1.1238x over previous
#include <cuda_runtime.h>
#include <math.h>
#include <stdint.h>

#define NB   4
#define TT   1024
#define HH   8
#define DD   64
#define DMOD 512
#define DFFV 1024
#define NLAY 6
#define ROWS (NB * TT)   // 4096
#define NH   (NB * HH)   // 32

#define QSCALE (0.125f * 1.4426950408889634f)

// ---------------- scratch (static device globals; no allocation) -------------
__device__ float g_h  [ROWS * DMOD];
__device__ float g_qkv[ROWS * 3 * DMOD];
__device__ float g_att[ROWS * DMOD];
__device__ float g_ff1[ROWS * DFFV];
__device__ float g_ff2[ROWS * DMOD];
__device__ float g_q  [NH * TT * DD];
__device__ float g_k  [NH * TT * DD];
__device__ float g_v  [NH * TT * DD];

// ---------------- embedding + positional encoding ----------------------------
__global__ void embed_kernel(const int* __restrict__ x, const float* __restrict__ emb)
{
    int row = blockIdx.x;
    int t   = row & (TT - 1);
    int tok = x[row];
    const float* e = emb + (size_t)tok * DMOD;
    for (int i = threadIdx.x; i < DMOD; i += blockDim.x) {
        double expo = -2.0 * (double)(i >> 1) / (double)DMOD;
        double ang  = (double)t * pow(10000.0, expo);
        float  p    = (i & 1) ? (float)cos(ang) : (float)sin(ang);
        g_h[(size_t)row * DMOD + i] = e[i] * 22.62741699796952f + p;  // sqrt(512)
    }
}

// ---------------- common PTX helpers -------------------------------------------
__device__ __forceinline__ uint32_t f2tf(float f)
{
    uint32_t r;
    asm("cvt.rna.tf32.f32 %0, %1;" : "=r"(r) : "f"(f));
    return r;
}
__device__ __forceinline__ void tfsplit(float x, uint32_t& big, uint32_t& small)
{
    big   = f2tf(x);
    small = f2tf(x - __uint_as_float(big));
}
__device__ __forceinline__ void mma_tf32(float* c, const uint32_t* a, uint32_t b0, uint32_t b1)
{
    asm volatile(
        "mma.sync.aligned.m16n8k8.row.col.f32.tf32.tf32.f32 "
        "{%0,%1,%2,%3}, {%4,%5,%6,%7}, {%8,%9}, {%0,%1,%2,%3};"
        : "+f"(c[0]), "+f"(c[1]), "+f"(c[2]), "+f"(c[3])
        : "r"(a[0]), "r"(a[1]), "r"(a[2]), "r"(a[3]), "r"(b0), "r"(b1));
}
__device__ __forceinline__ void cp_async16(uint32_t saddr, const void* gaddr)
{
    asm volatile("cp.async.cg.shared.global [%0], [%1], 16;" :: "r"(saddr), "l"(gaddr));
}
__device__ __forceinline__ void cp_commit() { asm volatile("cp.async.commit_group;"); }
template<int N> __device__ __forceinline__ void cp_wait() {
    asm volatile("cp.async.wait_group %0;" :: "n"(N));
}
__device__ __forceinline__ float ex2(float x)
{
    float r;
    asm("ex2.approx.ftz.f32 %0, %1;" : "=f"(r) : "f"(x));
    return r;
}

// ---------------- TF32 GEMM — R5-proven version (reg-staged, smem-side cvt) ---
#define LDA 20u
#define LDB 136u

template<bool RELU>
__global__ __launch_bounds__(256)
void gemm_tf32(const float* __restrict__ A, const float* __restrict__ B,
               const float* __restrict__ bias, float* __restrict__ C,
               int M, int N, int K)
{
    __shared__ uint32_t As[2][128 * LDA];
    __shared__ uint32_t Bs[2][16 * LDB];

    const int tid  = threadIdx.x;
    const int bm   = blockIdx.y * 128;
    const int bn   = blockIdx.x * 128;

    const int am = tid >> 1, ak = (tid & 1) * 8;
    const int bk = tid >> 4, bcol = (tid & 15) * 8;
    const float* Aptr = A + (size_t)(bm + am) * K + ak;
    const float* Bptr = B + (size_t)bk * N + bn + bcol;

    const int warp = tid >> 5, lane = tid & 31;
    const int gid  = lane >> 2, tig = lane & 3;
    const int wm   = (warp & 3) * 32;
    const int wn   = (warp >> 2) * 64;

    float c[2][8][4];
#pragma unroll
    for (int mt = 0; mt < 2; ++mt)
#pragma unroll
        for (int nt = 0; nt < 8; ++nt)
#pragma unroll
            for (int j = 0; j < 4; ++j) c[mt][nt][j] = 0.f;

    const int nIter = K >> 4;

    float4 ra0 = *(const float4*)(Aptr);
    float4 ra1 = *(const float4*)(Aptr + 4);
    float4 rb0 = *(const float4*)(Bptr);
    float4 rb1 = *(const float4*)(Bptr + 4);
    {
        uint32_t* ad = &As[0][am * LDA + ak];
        ad[0] = f2tf(ra0.x); ad[1] = f2tf(ra0.y); ad[2] = f2tf(ra0.z); ad[3] = f2tf(ra0.w);
        ad[4] = f2tf(ra1.x); ad[5] = f2tf(ra1.y); ad[6] = f2tf(ra1.z); ad[7] = f2tf(ra1.w);
        uint32_t* bd = &Bs[0][bk * LDB + bcol];
        bd[0] = f2tf(rb0.x); bd[1] = f2tf(rb0.y); bd[2] = f2tf(rb0.z); bd[3] = f2tf(rb0.w);
        bd[4] = f2tf(rb1.x); bd[5] = f2tf(rb1.y); bd[6] = f2tf(rb1.z); bd[7] = f2tf(rb1.w);
    }
    __syncthreads();

    for (int it = 0; it < nIter; ++it) {
        const int cur = it & 1;
        const bool more = (it + 1 < nIter);
        if (more) {
            const float* Ap = Aptr + (it + 1) * 16;
            const float* Bp = Bptr + (size_t)(it + 1) * 16 * N;
            ra0 = *(const float4*)(Ap);
            ra1 = *(const float4*)(Ap + 4);
            rb0 = *(const float4*)(Bp);
            rb1 = *(const float4*)(Bp + 4);
        }

        const uint32_t* Ac = As[cur];
        const uint32_t* Bc = Bs[cur];
#pragma unroll
        for (int ks = 0; ks < 2; ++ks) {
            const int kb = ks * 8;
            uint32_t a[2][4], b[8][2];
#pragma unroll
            for (int mt = 0; mt < 2; ++mt) {
                const int r = wm + mt * 16 + gid;
                a[mt][0] = Ac[(uint32_t)r * LDA + kb + tig];
                a[mt][1] = Ac[(uint32_t)(r + 8) * LDA + kb + tig];
                a[mt][2] = Ac[(uint32_t)r * LDA + kb + tig + 4];
                a[mt][3] = Ac[(uint32_t)(r + 8) * LDA + kb + tig + 4];
            }
#pragma unroll
            for (int nt = 0; nt < 8; ++nt) {
                const int col = wn + nt * 8 + gid;
                b[nt][0] = Bc[(uint32_t)(kb + tig) * LDB + col];
                b[nt][1] = Bc[(uint32_t)(kb + tig + 4) * LDB + col];
            }
#pragma unroll
            for (int mt = 0; mt < 2; ++mt)
#pragma unroll
                for (int nt = 0; nt < 8; ++nt)
                    mma_tf32(c[mt][nt], a[mt], b[nt][0], b[nt][1]);
        }

        if (more) {
            const int nxt = cur ^ 1;
            uint32_t* ad = &As[nxt][am * LDA + ak];
            ad[0] = f2tf(ra0.x); ad[1] = f2tf(ra0.y); ad[2] = f2tf(ra0.z); ad[3] = f2tf(ra0.w);
            ad[4] = f2tf(ra1.x); ad[5] = f2tf(ra1.y); ad[6] = f2tf(ra1.z); ad[7] = f2tf(ra1.w);
            uint32_t* bd = &Bs[nxt][bk * LDB + bcol];
            bd[0] = f2tf(rb0.x); bd[1] = f2tf(rb0.y); bd[2] = f2tf(rb0.z); bd[3] = f2tf(rb0.w);
            bd[4] = f2tf(rb1.x); bd[5] = f2tf(rb1.y); bd[6] = f2tf(rb1.z); bd[7] = f2tf(rb1.w);
            __syncthreads();
        }
    }

#pragma unroll
    for (int mt = 0; mt < 2; ++mt) {
        const int row0 = bm + wm + mt * 16 + gid;
#pragma unroll
        for (int nt = 0; nt < 8; ++nt) {
            const int coln = bn + wn + nt * 8 + 2 * tig;
            const float2 bv = *(const float2*)(bias + coln);
            float2 v0, v1;
            v0.x = c[mt][nt][0] + bv.x; v0.y = c[mt][nt][1] + bv.y;
            v1.x = c[mt][nt][2] + bv.x; v1.y = c[mt][nt][3] + bv.y;
            if (RELU) {
                v0.x = fmaxf(v0.x, 0.f); v0.y = fmaxf(v0.y, 0.f);
                v1.x = fmaxf(v1.x, 0.f); v1.y = fmaxf(v1.y, 0.f);
            }
            *(float2*)(C + (size_t)row0 * N + coln)       = v0;
            *(float2*)(C + (size_t)(row0 + 8) * N + coln) = v1;
        }
    }
}

// ---------------- split qkv into contiguous [nh][t][d] (fp32) ------------------
__global__ __launch_bounds__(384)
void split_qkv_kernel()
{
    int row = blockIdx.x;
    int n   = row >> 10;
    int t   = row & (TT - 1);
    int c0  = threadIdx.x * 4;
    float4 v = *(const float4*)(g_qkv + (size_t)row * 1536 + c0);
    float vals[4] = {v.x, v.y, v.z, v.w};
#pragma unroll
    for (int u = 0; u < 4; ++u) {
        int c = c0 + u;
        int h = c / 192;
        int r = c - h * 192;
        int d = r / 3;
        int j = r - d * 3;
        size_t dst = ((size_t)(n * HH + h) * TT + t) * DD + d;
        if (j == 0)      g_q[dst] = vals[u] * QSCALE;
        else if (j == 1) g_k[dst] = vals[u];
        else             g_v[dst] = vals[u];
    }
}

// ---------------- FlashAttention-2, compensated tf32, 32-key tiles -------------
// grid (T/64, NH); block 128 (4 warps, 16 query rows each); dynamic smem 44KB.
#define KT   32
#define LDK  68
#define LDV  72
#define LDP  36
#define OFF_K0 0
#define OFF_K1 (KT * LDK)                        // 2176
#define OFF_V0 (2 * KT * LDK)                    // 4352
#define OFF_V1 (OFF_V0 + KT * LDV)               // 6656
#define OFF_P  (OFF_V0 + 2 * KT * LDV)           // 8960
#define ATTN_SMEM_FLOATS (OFF_P + 4 * 16 * LDP)  // 11264
#define ATTN_SMEM_BYTES  (ATTN_SMEM_FLOATS * 4)  // 45056

__global__ __launch_bounds__(128)
void attn_mma_kernel()
{
    extern __shared__ float sm[];

    const int tid  = threadIdx.x;
    const int warp = tid >> 5, lane = tid & 31;
    const int gid  = lane >> 2, tig = lane & 3;
    const int qt   = gridDim.x - 1 - blockIdx.x;   // heavy q-tiles first
    const int nh   = blockIdx.y;
    const int row0 = qt * 64 + warp * 16;

    const float* kb = g_k + (size_t)nh * TT * DD;
    const float* vb = g_v + (size_t)nh * TT * DD;

    const uint32_t sbase = (uint32_t)__cvta_generic_to_shared(sm);

    uint32_t qfb[8][4], qfs[8][4];
    {
        const float* qp = g_q + ((size_t)nh * TT + row0) * DD;
#pragma unroll
        for (int kt = 0; kt < 8; ++kt) {
            tfsplit(qp[gid * DD + kt * 8 + tig],           qfb[kt][0], qfs[kt][0]);
            tfsplit(qp[(gid + 8) * DD + kt * 8 + tig],     qfb[kt][1], qfs[kt][1]);
            tfsplit(qp[gid * DD + kt * 8 + tig + 4],       qfb[kt][2], qfs[kt][2]);
            tfsplit(qp[(gid + 8) * DD + kt * 8 + tig + 4], qfb[kt][3], qfs[kt][3]);
        }
    }

    float o[8][4];
#pragma unroll
    for (int nt = 0; nt < 8; ++nt)
#pragma unroll
        for (int j = 0; j < 4; ++j) o[nt][j] = 0.f;
    float m0 = -INFINITY, m1 = -INFINITY, l0 = 0.f, l1 = 0.f;

    const int ntiles = 2 * qt + 2;               // 32-key tiles, causal range

    // one 32x64 K tile + one 32x64 V tile = 512 float4 each; 4 per thread
    auto prefetch = [&](int t) {
        const size_t gb = (size_t)t * KT * DD;
        const uint32_t kOff = (t & 1) ? OFF_K1 : OFF_K0;
        const uint32_t vOff = (t & 1) ? OFF_V1 : OFF_V0;
#pragma unroll
        for (int i = 0; i < 4; ++i) {
            int idx = i * 128 + tid;             // 0..511
            int r   = idx >> 4;                  // 0..31
            int c4  = (idx & 15) * 4;            // 0..60
            cp_async16(sbase + (kOff + r * LDK + c4) * 4, kb + gb + r * DD + c4);
            cp_async16(sbase + (vOff + r * LDV + c4) * 4, vb + gb + r * DD + c4);
        }
        cp_commit();
    };

    prefetch(0);

    float* Pw = sm + OFF_P + warp * 16 * LDP;

#pragma unroll 1
    for (int kt_i = 0; kt_i < ntiles; ++kt_i) {
        cp_wait<0>();          // tile kt_i resident
        __syncthreads();       // all warps done reading previous buffer
        if (kt_i + 1 < ntiles) prefetch(kt_i + 1);  // overlaps compute below

        const float* Kt = sm + ((kt_i & 1) ? OFF_K1 : OFF_K0);
        const float* Vt = sm + ((kt_i & 1) ? OFF_V1 : OFF_V0);

        // ---- S = Q @ K^T (16x32 per warp), compensated ----
        float cs[4][4];
#pragma unroll
        for (int nt = 0; nt < 4; ++nt) {
#pragma unroll
            for (int j = 0; j < 4; ++j) cs[nt][j] = 0.f;
#pragma unroll
            for (int dk = 0; dk < 8; ++dk) {
                uint32_t bb0, bs0, bb1, bs1;
                tfsplit(Kt[(nt * 8 + gid) * LDK + dk * 8 + tig],     bb0, bs0);
                tfsplit(Kt[(nt * 8 + gid) * LDK + dk * 8 + tig + 4], bb1, bs1);
                mma_tf32(cs[nt], qfb[dk], bb0, bb1);
                mma_tf32(cs[nt], qfb[dk], bs0, bs1);
                mma_tf32(cs[nt], qfs[dk], bb0, bb1);
            }
        }

        // ---- causal mask (only the last two tiles can cross the diagonal) ----
        if (kt_i >= 2 * qt) {
            const int rl0 = row0 + gid;
            const int rl1 = rl0 + 8;
#pragma unroll
            for (int nt = 0; nt < 4; ++nt) {
                int j = kt_i * KT + nt * 8 + 2 * tig;
                if (j     > rl0) cs[nt][0] = -INFINITY;
                if (j + 1 > rl0) cs[nt][1] = -INFINITY;
                if (j     > rl1) cs[nt][2] = -INFINITY;
                if (j + 1 > rl1) cs[nt][3] = -INFINITY;
            }
        }

        // ---- online softmax (exp2 domain) ----
        float mx0 = -INFINITY, mx1 = -INFINITY;
#pragma unroll
        for (int nt = 0; nt < 4; ++nt) {
            mx0 = fmaxf(mx0, fmaxf(cs[nt][0], cs[nt][1]));
            mx1 = fmaxf(mx1, fmaxf(cs[nt][2], cs[nt][3]));
        }
        mx0 = fmaxf(mx0, __shfl_xor_sync(0xffffffffu, mx0, 1));
        mx0 = fmaxf(mx0, __shfl_xor_sync(0xffffffffu, mx0, 2));
        mx1 = fmaxf(mx1, __shfl_xor_sync(0xffffffffu, mx1, 1));
        mx1 = fmaxf(mx1, __shfl_xor_sync(0xffffffffu, mx1, 2));

        const float mn0 = fmaxf(m0, mx0);
        const float mn1 = fmaxf(m1, mx1);
        const float cor0 = ex2(m0 - mn0);
        const float cor1 = ex2(m1 - mn1);
        l0 *= cor0; l1 *= cor1;
#pragma unroll
        for (int nt = 0; nt < 8; ++nt) {
            o[nt][0] *= cor0; o[nt][1] *= cor0;
            o[nt][2] *= cor1; o[nt][3] *= cor1;
        }

        float rs0 = 0.f, rs1 = 0.f;
#pragma unroll
        for (int nt = 0; nt < 4; ++nt) {
            float p0 = ex2(cs[nt][0] - mn0);
            float p1 = ex2(cs[nt][1] - mn0);
            float p2 = ex2(cs[nt][2] - mn1);
            float p3 = ex2(cs[nt][3] - mn1);
            rs0 += p0 + p1; rs1 += p2 + p3;
            int col = nt * 8 + 2 * tig;
            *(float2*)(Pw + gid * LDP + col)       = make_float2(p0, p1);
            *(float2*)(Pw + (gid + 8) * LDP + col) = make_float2(p2, p3);
        }
        rs0 += __shfl_xor_sync(0xffffffffu, rs0, 1);
        rs0 += __shfl_xor_sync(0xffffffffu, rs0, 2);
        rs1 += __shfl_xor_sync(0xffffffffu, rs1, 1);
        rs1 += __shfl_xor_sync(0xffffffffu, rs1, 2);
        l0 += rs0; l1 += rs1;
        m0 = mn0; m1 = mn1;

        __syncwarp();

        // ---- O += P @ V (16x64 per warp), compensated ----
#pragma unroll
        for (int kk = 0; kk < 4; ++kk) {
            uint32_t ab[4], as_[4];
            tfsplit(Pw[gid * LDP + kk * 8 + tig],           ab[0], as_[0]);
            tfsplit(Pw[(gid + 8) * LDP + kk * 8 + tig],     ab[1], as_[1]);
            tfsplit(Pw[gid * LDP + kk * 8 + tig + 4],       ab[2], as_[2]);
            tfsplit(Pw[(gid + 8) * LDP + kk * 8 + tig + 4], ab[3], as_[3]);
#pragma unroll
            for (int nt = 0; nt < 8; ++nt) {
                uint32_t bb0, bs0, bb1, bs1;
                tfsplit(Vt[(kk * 8 + tig) * LDV + nt * 8 + gid],     bb0, bs0);
                tfsplit(Vt[(kk * 8 + tig + 4) * LDV + nt * 8 + gid], bb1, bs1);
                mma_tf32(o[nt], ab,  bb0, bb1);
                mma_tf32(o[nt], ab,  bs0, bs1);
                mma_tf32(o[nt], as_, bb0, bb1);
            }
        }
    }

    const float i0 = 1.f / l0;
    const float i1 = 1.f / l1;
    const int n = nh >> 3, hh = nh & 7;
    const int rg0 = row0 + gid;
#pragma unroll
    for (int nt = 0; nt < 8; ++nt) {
        int col = hh * DD + nt * 8 + 2 * tig;
        *(float2*)(g_att + (size_t)(n * TT + rg0) * DMOD + col) =
            make_float2(o[nt][0] * i0, o[nt][1] * i0);
        *(float2*)(g_att + (size_t)(n * TT + rg0 + 8) * DMOD + col) =
            make_float2(o[nt][2] * i1, o[nt][3] * i1);
    }
}

// ---------------- fused residual add + LayerNorm ------------------------------
__global__ __launch_bounds__(256)
void add_ln_kernel(const float* __restrict__ a, const float* __restrict__ b,
                   const float* __restrict__ gamma, const float* __restrict__ beta,
                   float* __restrict__ out)
{
    int row = blockIdx.x;
    int tid = threadIdx.x;
    const float* ar = a + (size_t)row * DMOD;
    const float* br = b + (size_t)row * DMOD;

    float x0 = ar[tid]       + br[tid];
    float x1 = ar[tid + 256] + br[tid + 256];

    float sum = x0 + x1;
    float sq  = x0 * x0 + x1 * x1;
#pragma unroll
    for (int off = 16; off; off >>= 1) {
        sum += __shfl_xor_sync(0xffffffffu, sum, off);
        sq  += __shfl_xor_sync(0xffffffffu, sq,  off);
    }
    __shared__ float s1[8], s2[8];
    int wid = tid >> 5, lane = tid & 31;
    if (lane == 0) { s1[wid] = sum; s2[wid] = sq; }
    __syncthreads();
    float S = 0.f, Q = 0.f;
#pragma unroll
    for (int i = 0; i < 8; ++i) { S += s1[i]; Q += s2[i]; }

    float mean = S * (1.f / DMOD);
    float var  = Q * (1.f / DMOD) - mean * mean;
    float rstd = 1.f / sqrtf(var + 1e-3f);

    out[(size_t)row * DMOD + tid]       = gamma[tid]       * (x0 - mean) * rstd + beta[tid];
    out[(size_t)row * DMOD + tid + 256] = gamma[tid + 256] * (x1 - mean) * rstd + beta[tid + 256];
}

// ---------------- launch ------------------------------------------------------
extern "C" void kernel_launch(void* const* d_in, const int* in_sizes, int n_in,
                              void* d_out, int out_size)
{
    const int*   x     = (const int*)  d_in[0];
    const float* emb   = (const float*)d_in[1];
    const float* Wqkv  = (const float*)d_in[2];
    const float* bqkv  = (const float*)d_in[3];
    const float* Wff   = (const float*)d_in[4];
    const float* bff   = (const float*)d_in[5];
    const float* Wo    = (const float*)d_in[6];
    const float* bo    = (const float*)d_in[7];
    const float* g1    = (const float*)d_in[8];
    const float* beta1 = (const float*)d_in[9];
    const float* g2    = (const float*)d_in[10];
    const float* beta2 = (const float*)d_in[11];
    float* out = (float*)d_out;

    float *h, *qkv, *att, *ff1, *ff2;
    cudaGetSymbolAddress((void**)&h,   g_h);
    cudaGetSymbolAddress((void**)&qkv, g_qkv);
    cudaGetSymbolAddress((void**)&att, g_att);
    cudaGetSymbolAddress((void**)&ff1, g_ff1);
    cudaGetSymbolAddress((void**)&ff2, g_ff2);

    cudaFuncSetAttribute(attn_mma_kernel,
                         cudaFuncAttributeMaxDynamicSharedMemorySize, ATTN_SMEM_BYTES);

    embed_kernel<<<ROWS, 128>>>(x, emb);

    for (int l = 0; l < NLAY; ++l) {
        gemm_tf32<false><<<dim3(1536 / 128, ROWS / 128), 256>>>(
            h, Wqkv + (size_t)l * DMOD * 3 * DMOD, bqkv + (size_t)l * 3 * DMOD,
            qkv, ROWS, 3 * DMOD, DMOD);

        split_qkv_kernel<<<ROWS, 384>>>();

        attn_mma_kernel<<<dim3(TT / 64, NH), 128, ATTN_SMEM_BYTES>>>();

        add_ln_kernel<<<ROWS, 256>>>(h, att, g1 + (size_t)l * DMOD, beta1 + (size_t)l * DMOD, h);

        gemm_tf32<true><<<dim3(DFFV / 128, ROWS / 128), 256>>>(
            h, Wff + (size_t)l * DMOD * DFFV, bff + (size_t)l * DFFV,
            ff1, ROWS, DFFV, DMOD);

        gemm_tf32<false><<<dim3(DMOD / 128, ROWS / 128), 256>>>(
            ff1, Wo + (size_t)l * DFFV * DMOD, bo + (size_t)l * DMOD,
            ff2, ROWS, DMOD, DFFV);

        add_ln_kernel<<<ROWS, 256>>>(h, ff2, g2 + (size_t)l * DMOD, beta2 + (size_t)l * DMOD,
                                     (l == NLAY - 1) ? out : h);
    }
}

// round 8
// speedup vs baseline: 1.1684x; 1.0397x over previous
#include <cuda_runtime.h>
#include <math.h>
#include <stdint.h>

#define NB   4
#define TT   1024
#define HH   8
#define DD   64
#define DMOD 512
#define DFFV 1024
#define NLAY 6
#define ROWS (NB * TT)   // 4096
#define NH   (NB * HH)   // 32

#define QSCALE (0.125f * 1.4426950408889634f)

// ---------------- scratch (static device globals; no allocation) -------------
__device__ float g_h   [ROWS * DMOD];
__device__ float g_htf [ROWS * DMOD];           // tf32-rounded copy of g_h
__device__ float g_qkv [ROWS * 3 * DMOD];
__device__ float g_att [ROWS * DMOD];
__device__ float g_ff1 [ROWS * DFFV];           // tf32-rounded relu output
__device__ float g_ff2 [ROWS * DMOD];
__device__ float g_q   [NH * TT * DD];
__device__ float g_k   [NH * TT * DD];
__device__ float g_v   [NH * TT * DD];
// tf32-pre-rounded weights
__device__ float g_wqkv[NLAY * DMOD * 3 * DMOD];
__device__ float g_wff [NLAY * DMOD * DFFV];
__device__ float g_wo  [NLAY * DFFV * DMOD];

// ---------------- common PTX helpers -------------------------------------------
__device__ __forceinline__ uint32_t f2tf(float f)
{
    uint32_t r;
    asm("cvt.rna.tf32.f32 %0, %1;" : "=r"(r) : "f"(f));
    return r;
}
__device__ __forceinline__ float f2tff(float f) { return __uint_as_float(f2tf(f)); }
__device__ __forceinline__ void tfsplit(float x, uint32_t& big, uint32_t& small)
{
    big   = f2tf(x);
    small = f2tf(x - __uint_as_float(big));
}
__device__ __forceinline__ void mma_tf32(float* c, const uint32_t* a, uint32_t b0, uint32_t b1)
{
    asm volatile(
        "mma.sync.aligned.m16n8k8.row.col.f32.tf32.tf32.f32 "
        "{%0,%1,%2,%3}, {%4,%5,%6,%7}, {%8,%9}, {%0,%1,%2,%3};"
        : "+f"(c[0]), "+f"(c[1]), "+f"(c[2]), "+f"(c[3])
        : "r"(a[0]), "r"(a[1]), "r"(a[2]), "r"(a[3]), "r"(b0), "r"(b1));
}
__device__ __forceinline__ void cp_async16(uint32_t saddr, const void* gaddr)
{
    asm volatile("cp.async.cg.shared.global [%0], [%1], 16;" :: "r"(saddr), "l"(gaddr));
}
__device__ __forceinline__ void cp_commit() { asm volatile("cp.async.commit_group;"); }
template<int N> __device__ __forceinline__ void cp_wait() {
    asm volatile("cp.async.wait_group %0;" :: "n"(N));
}
__device__ __forceinline__ float ex2(float x)
{
    float r;
    asm("ex2.approx.ftz.f32 %0, %1;" : "=f"(r) : "f"(x));
    return r;
}

// ---------------- weight pre-rounding prepass ----------------------------------
__global__ __launch_bounds__(256)
void round_copy_kernel(const float* __restrict__ src, float* __restrict__ dst, int n4)
{
    int i = blockIdx.x * blockDim.x + threadIdx.x;
    for (; i < n4; i += gridDim.x * blockDim.x) {
        float4 v = ((const float4*)src)[i];
        v.x = f2tff(v.x); v.y = f2tff(v.y); v.z = f2tff(v.z); v.w = f2tff(v.w);
        ((float4*)dst)[i] = v;
    }
}

// ---------------- embedding + positional encoding ----------------------------
__global__ void embed_kernel(const int* __restrict__ x, const float* __restrict__ emb)
{
    int row = blockIdx.x;
    int t   = row & (TT - 1);
    int tok = x[row];
    const float* e = emb + (size_t)tok * DMOD;
    for (int i = threadIdx.x; i < DMOD; i += blockDim.x) {
        double expo = -2.0 * (double)(i >> 1) / (double)DMOD;
        double ang  = (double)t * pow(10000.0, expo);
        float  p    = (i & 1) ? (float)cos(ang) : (float)sin(ang);
        float  val  = e[i] * 22.62741699796952f + p;  // sqrt(512)
        g_h  [(size_t)row * DMOD + i] = val;
        g_htf[(size_t)row * DMOD + i] = f2tff(val);
    }
}

// ---------------- TF32 GEMM — cvt-free, 3-stage cp.async pipeline --------------
// A and B are PRE-ROUNDED tf32 values stored as float. MODE 0: plain fp32 out;
// MODE 1: relu + tf32-rounded out.
#define LDA 20u
#define LDB 136u
#define STG 3

template<int MODE>
__global__ __launch_bounds__(256)
void gemm_tf32(const float* __restrict__ A, const float* __restrict__ B,
               const float* __restrict__ bias, float* __restrict__ C,
               int M, int N, int K)
{
    __shared__ float As[STG][128 * LDA];
    __shared__ float Bs[STG][16 * LDB];

    const int tid  = threadIdx.x;
    const int bm   = blockIdx.y * 128;
    const int bn   = blockIdx.x * 128;

    const int am = tid >> 1, ak = (tid & 1) * 8;
    const int bk = tid >> 4, bcol = (tid & 15) * 8;

    const uint32_t sA = (uint32_t)__cvta_generic_to_shared(&As[0][0]);
    const uint32_t sB = (uint32_t)__cvta_generic_to_shared(&Bs[0][0]);

    const int warp = tid >> 5, lane = tid & 31;
    const int gid  = lane >> 2, tig = lane & 3;
    const int wm   = (warp & 3) * 32;
    const int wn   = (warp >> 2) * 64;

    float c[2][8][4];
#pragma unroll
    for (int mt = 0; mt < 2; ++mt)
#pragma unroll
        for (int nt = 0; nt < 8; ++nt)
#pragma unroll
            for (int j = 0; j < 4; ++j) c[mt][nt][j] = 0.f;

    const int nIter = K >> 4;

    auto issue = [&](int t) {
        const int buf = t % STG;
        const float* Ap = A + (size_t)(bm + am) * K + t * 16 + ak;
        const float* Bp = B + (size_t)(t * 16 + bk) * N + bn + bcol;
        uint32_t sa = sA + (buf * 128 * LDA + am * LDA + ak) * 4;
        uint32_t sb = sB + (buf * 16 * LDB + bk * LDB + bcol) * 4;
        cp_async16(sa,      Ap);
        cp_async16(sa + 16, Ap + 4);
        cp_async16(sb,      Bp);
        cp_async16(sb + 16, Bp + 4);
        cp_commit();
    };

    issue(0);
    if (nIter > 1) issue(1);

    for (int it = 0; it < nIter; ++it) {
        if (it + 1 < nIter) cp_wait<1>(); else cp_wait<0>();
        __syncthreads();
        if (it + 2 < nIter) issue(it + 2);

        const float* Ac = As[it % STG];
        const float* Bc = Bs[it % STG];
#pragma unroll
        for (int ks = 0; ks < 2; ++ks) {
            const int kb = ks * 8;
            uint32_t a[2][4], b[8][2];
#pragma unroll
            for (int mt = 0; mt < 2; ++mt) {
                const int r = wm + mt * 16 + gid;
                a[mt][0] = __float_as_uint(Ac[(uint32_t)r * LDA + kb + tig]);
                a[mt][1] = __float_as_uint(Ac[(uint32_t)(r + 8) * LDA + kb + tig]);
                a[mt][2] = __float_as_uint(Ac[(uint32_t)r * LDA + kb + tig + 4]);
                a[mt][3] = __float_as_uint(Ac[(uint32_t)(r + 8) * LDA + kb + tig + 4]);
            }
#pragma unroll
            for (int nt = 0; nt < 8; ++nt) {
                const int col = wn + nt * 8 + gid;
                b[nt][0] = __float_as_uint(Bc[(uint32_t)(kb + tig) * LDB + col]);
                b[nt][1] = __float_as_uint(Bc[(uint32_t)(kb + tig + 4) * LDB + col]);
            }
#pragma unroll
            for (int mt = 0; mt < 2; ++mt)
#pragma unroll
                for (int nt = 0; nt < 8; ++nt)
                    mma_tf32(c[mt][nt], a[mt], b[nt][0], b[nt][1]);
        }
    }

    // ---- epilogue ----
#pragma unroll
    for (int mt = 0; mt < 2; ++mt) {
        const int row0 = bm + wm + mt * 16 + gid;
#pragma unroll
        for (int nt = 0; nt < 8; ++nt) {
            const int coln = bn + wn + nt * 8 + 2 * tig;
            const float2 bv = *(const float2*)(bias + coln);
            float2 v0, v1;
            v0.x = c[mt][nt][0] + bv.x; v0.y = c[mt][nt][1] + bv.y;
            v1.x = c[mt][nt][2] + bv.x; v1.y = c[mt][nt][3] + bv.y;
            if (MODE == 1) {
                v0.x = f2tff(fmaxf(v0.x, 0.f)); v0.y = f2tff(fmaxf(v0.y, 0.f));
                v1.x = f2tff(fmaxf(v1.x, 0.f)); v1.y = f2tff(fmaxf(v1.y, 0.f));
            }
            *(float2*)(C + (size_t)row0 * N + coln)       = v0;
            *(float2*)(C + (size_t)(row0 + 8) * N + coln) = v1;
        }
    }
}

// ---------------- split qkv into contiguous [nh][t][d] (fp32) ------------------
__global__ __launch_bounds__(384)
void split_qkv_kernel()
{
    int row = blockIdx.x;
    int n   = row >> 10;
    int t   = row & (TT - 1);
    int c0  = threadIdx.x * 4;
    float4 v = *(const float4*)(g_qkv + (size_t)row * 1536 + c0);
    float vals[4] = {v.x, v.y, v.z, v.w};
#pragma unroll
    for (int u = 0; u < 4; ++u) {
        int c = c0 + u;
        int h = c / 192;
        int r = c - h * 192;
        int d = r / 3;
        int j = r - d * 3;
        size_t dst = ((size_t)(n * HH + h) * TT + t) * DD + d;
        if (j == 0)      g_q[dst] = vals[u] * QSCALE;
        else if (j == 1) g_k[dst] = vals[u];
        else             g_v[dst] = vals[u];
    }
}

// ---------------- FlashAttention-2, compensated tf32, 32-key tiles (R7) --------
#define KT   32
#define LDK  68
#define LDV  72
#define LDP  36
#define OFF_K0 0
#define OFF_K1 (KT * LDK)
#define OFF_V0 (2 * KT * LDK)
#define OFF_V1 (OFF_V0 + KT * LDV)
#define OFF_P  (OFF_V0 + 2 * KT * LDV)
#define ATTN_SMEM_FLOATS (OFF_P + 4 * 16 * LDP)
#define ATTN_SMEM_BYTES  (ATTN_SMEM_FLOATS * 4)   // 45056

__global__ __launch_bounds__(128)
void attn_mma_kernel()
{
    extern __shared__ float sm[];

    const int tid  = threadIdx.x;
    const int warp = tid >> 5, lane = tid & 31;
    const int gid  = lane >> 2, tig = lane & 3;
    const int qt   = gridDim.x - 1 - blockIdx.x;
    const int nh   = blockIdx.y;
    const int row0 = qt * 64 + warp * 16;

    const float* kb = g_k + (size_t)nh * TT * DD;
    const float* vb = g_v + (size_t)nh * TT * DD;

    const uint32_t sbase = (uint32_t)__cvta_generic_to_shared(sm);

    uint32_t qfb[8][4], qfs[8][4];
    {
        const float* qp = g_q + ((size_t)nh * TT + row0) * DD;
#pragma unroll
        for (int kt = 0; kt < 8; ++kt) {
            tfsplit(qp[gid * DD + kt * 8 + tig],           qfb[kt][0], qfs[kt][0]);
            tfsplit(qp[(gid + 8) * DD + kt * 8 + tig],     qfb[kt][1], qfs[kt][1]);
            tfsplit(qp[gid * DD + kt * 8 + tig + 4],       qfb[kt][2], qfs[kt][2]);
            tfsplit(qp[(gid + 8) * DD + kt * 8 + tig + 4], qfb[kt][3], qfs[kt][3]);
        }
    }

    float o[8][4];
#pragma unroll
    for (int nt = 0; nt < 8; ++nt)
#pragma unroll
        for (int j = 0; j < 4; ++j) o[nt][j] = 0.f;
    float m0 = -INFINITY, m1 = -INFINITY, l0 = 0.f, l1 = 0.f;

    const int ntiles = 2 * qt + 2;

    auto prefetch = [&](int t) {
        const size_t gb = (size_t)t * KT * DD;
        const uint32_t kOff = (t & 1) ? OFF_K1 : OFF_K0;
        const uint32_t vOff = (t & 1) ? OFF_V1 : OFF_V0;
#pragma unroll
        for (int i = 0; i < 4; ++i) {
            int idx = i * 128 + tid;
            int r   = idx >> 4;
            int c4  = (idx & 15) * 4;
            cp_async16(sbase + (kOff + r * LDK + c4) * 4, kb + gb + r * DD + c4);
            cp_async16(sbase + (vOff + r * LDV + c4) * 4, vb + gb + r * DD + c4);
        }
        cp_commit();
    };

    prefetch(0);

    float* Pw = sm + OFF_P + warp * 16 * LDP;

#pragma unroll 1
    for (int kt_i = 0; kt_i < ntiles; ++kt_i) {
        cp_wait<0>();
        __syncthreads();
        if (kt_i + 1 < ntiles) prefetch(kt_i + 1);

        const float* Kt = sm + ((kt_i & 1) ? OFF_K1 : OFF_K0);
        const float* Vt = sm + ((kt_i & 1) ? OFF_V1 : OFF_V0);

        float cs[4][4];
#pragma unroll
        for (int nt = 0; nt < 4; ++nt) {
#pragma unroll
            for (int j = 0; j < 4; ++j) cs[nt][j] = 0.f;
#pragma unroll
            for (int dk = 0; dk < 8; ++dk) {
                uint32_t bb0, bs0, bb1, bs1;
                tfsplit(Kt[(nt * 8 + gid) * LDK + dk * 8 + tig],     bb0, bs0);
                tfsplit(Kt[(nt * 8 + gid) * LDK + dk * 8 + tig + 4], bb1, bs1);
                mma_tf32(cs[nt], qfb[dk], bb0, bb1);
                mma_tf32(cs[nt], qfb[dk], bs0, bs1);
                mma_tf32(cs[nt], qfs[dk], bb0, bb1);
            }
        }

        if (kt_i >= 2 * qt) {
            const int rl0 = row0 + gid;
            const int rl1 = rl0 + 8;
#pragma unroll
            for (int nt = 0; nt < 4; ++nt) {
                int j = kt_i * KT + nt * 8 + 2 * tig;
                if (j     > rl0) cs[nt][0] = -INFINITY;
                if (j + 1 > rl0) cs[nt][1] = -INFINITY;
                if (j     > rl1) cs[nt][2] = -INFINITY;
                if (j + 1 > rl1) cs[nt][3] = -INFINITY;
            }
        }

        float mx0 = -INFINITY, mx1 = -INFINITY;
#pragma unroll
        for (int nt = 0; nt < 4; ++nt) {
            mx0 = fmaxf(mx0, fmaxf(cs[nt][0], cs[nt][1]));
            mx1 = fmaxf(mx1, fmaxf(cs[nt][2], cs[nt][3]));
        }
        mx0 = fmaxf(mx0, __shfl_xor_sync(0xffffffffu, mx0, 1));
        mx0 = fmaxf(mx0, __shfl_xor_sync(0xffffffffu, mx0, 2));
        mx1 = fmaxf(mx1, __shfl_xor_sync(0xffffffffu, mx1, 1));
        mx1 = fmaxf(mx1, __shfl_xor_sync(0xffffffffu, mx1, 2));

        const float mn0 = fmaxf(m0, mx0);
        const float mn1 = fmaxf(m1, mx1);
        const float cor0 = ex2(m0 - mn0);
        const float cor1 = ex2(m1 - mn1);
        l0 *= cor0; l1 *= cor1;
#pragma unroll
        for (int nt = 0; nt < 8; ++nt) {
            o[nt][0] *= cor0; o[nt][1] *= cor0;
            o[nt][2] *= cor1; o[nt][3] *= cor1;
        }

        float rs0 = 0.f, rs1 = 0.f;
#pragma unroll
        for (int nt = 0; nt < 4; ++nt) {
            float p0 = ex2(cs[nt][0] - mn0);
            float p1 = ex2(cs[nt][1] - mn0);
            float p2 = ex2(cs[nt][2] - mn1);
            float p3 = ex2(cs[nt][3] - mn1);
            rs0 += p0 + p1; rs1 += p2 + p3;
            int col = nt * 8 + 2 * tig;
            *(float2*)(Pw + gid * LDP + col)       = make_float2(p0, p1);
            *(float2*)(Pw + (gid + 8) * LDP + col) = make_float2(p2, p3);
        }
        rs0 += __shfl_xor_sync(0xffffffffu, rs0, 1);
        rs0 += __shfl_xor_sync(0xffffffffu, rs0, 2);
        rs1 += __shfl_xor_sync(0xffffffffu, rs1, 1);
        rs1 += __shfl_xor_sync(0xffffffffu, rs1, 2);
        l0 += rs0; l1 += rs1;
        m0 = mn0; m1 = mn1;

        __syncwarp();

#pragma unroll
        for (int kk = 0; kk < 4; ++kk) {
            uint32_t ab[4], as_[4];
            tfsplit(Pw[gid * LDP + kk * 8 + tig],           ab[0], as_[0]);
            tfsplit(Pw[(gid + 8) * LDP + kk * 8 + tig],     ab[1], as_[1]);
            tfsplit(Pw[gid * LDP + kk * 8 + tig + 4],       ab[2], as_[2]);
            tfsplit(Pw[(gid + 8) * LDP + kk * 8 + tig + 4], ab[3], as_[3]);
#pragma unroll
            for (int nt = 0; nt < 8; ++nt) {
                uint32_t bb0, bs0, bb1, bs1;
                tfsplit(Vt[(kk * 8 + tig) * LDV + nt * 8 + gid],     bb0, bs0);
                tfsplit(Vt[(kk * 8 + tig + 4) * LDV + nt * 8 + gid], bb1, bs1);
                mma_tf32(o[nt], ab,  bb0, bb1);
                mma_tf32(o[nt], ab,  bs0, bs1);
                mma_tf32(o[nt], as_, bb0, bb1);
            }
        }
    }

    const float i0 = 1.f / l0;
    const float i1 = 1.f / l1;
    const int n = nh >> 3, hh = nh & 7;
    const int rg0 = row0 + gid;
#pragma unroll
    for (int nt = 0; nt < 8; ++nt) {
        int col = hh * DD + nt * 8 + 2 * tig;
        *(float2*)(g_att + (size_t)(n * TT + rg0) * DMOD + col) =
            make_float2(o[nt][0] * i0, o[nt][1] * i0);
        *(float2*)(g_att + (size_t)(n * TT + rg0 + 8) * DMOD + col) =
            make_float2(o[nt][2] * i1, o[nt][3] * i1);
    }
}

// ---------------- fused residual add + LayerNorm -------------------------------
// WRITE_TF: additionally write a tf32-rounded copy to g_htf (next GEMM's A).
template<bool WRITE_TF>
__global__ __launch_bounds__(256)
void add_ln_kernel(const float* __restrict__ a, const float* __restrict__ b,
                   const float* __restrict__ gamma, const float* __restrict__ beta,
                   float* __restrict__ out)
{
    int row = blockIdx.x;
    int tid = threadIdx.x;
    const float* ar = a + (size_t)row * DMOD;
    const float* br = b + (size_t)row * DMOD;

    float x0 = ar[tid]       + br[tid];
    float x1 = ar[tid + 256] + br[tid + 256];

    float sum = x0 + x1;
    float sq  = x0 * x0 + x1 * x1;
#pragma unroll
    for (int off = 16; off; off >>= 1) {
        sum += __shfl_xor_sync(0xffffffffu, sum, off);
        sq  += __shfl_xor_sync(0xffffffffu, sq,  off);
    }
    __shared__ float s1[8], s2[8];
    int wid = tid >> 5, lane = tid & 31;
    if (lane == 0) { s1[wid] = sum; s2[wid] = sq; }
    __syncthreads();
    float S = 0.f, Q = 0.f;
#pragma unroll
    for (int i = 0; i < 8; ++i) { S += s1[i]; Q += s2[i]; }

    float mean = S * (1.f / DMOD);
    float var  = Q * (1.f / DMOD) - mean * mean;
    float rstd = 1.f / sqrtf(var + 1e-3f);

    float y0 = gamma[tid]       * (x0 - mean) * rstd + beta[tid];
    float y1 = gamma[tid + 256] * (x1 - mean) * rstd + beta[tid + 256];
    out[(size_t)row * DMOD + tid]       = y0;
    out[(size_t)row * DMOD + tid + 256] = y1;
    if (WRITE_TF) {
        g_htf[(size_t)row * DMOD + tid]       = f2tff(y0);
        g_htf[(size_t)row * DMOD + tid + 256] = f2tff(y1);
    }
}

// ---------------- launch ------------------------------------------------------
extern "C" void kernel_launch(void* const* d_in, const int* in_sizes, int n_in,
                              void* d_out, int out_size)
{
    const int*   x     = (const int*)  d_in[0];
    const float* emb   = (const float*)d_in[1];
    const float* Wqkv  = (const float*)d_in[2];
    const float* bqkv  = (const float*)d_in[3];
    const float* Wff   = (const float*)d_in[4];
    const float* bff   = (const float*)d_in[5];
    const float* Wo    = (const float*)d_in[6];
    const float* bo    = (const float*)d_in[7];
    const float* g1    = (const float*)d_in[8];
    const float* beta1 = (const float*)d_in[9];
    const float* g2    = (const float*)d_in[10];
    const float* beta2 = (const float*)d_in[11];
    float* out = (float*)d_out;

    float *h, *qkv, *att, *ff1, *ff2, *htf, *wqkv, *wff, *wo;
    cudaGetSymbolAddress((void**)&h,    g_h);
    cudaGetSymbolAddress((void**)&htf,  g_htf);
    cudaGetSymbolAddress((void**)&qkv,  g_qkv);
    cudaGetSymbolAddress((void**)&att,  g_att);
    cudaGetSymbolAddress((void**)&ff1,  g_ff1);
    cudaGetSymbolAddress((void**)&ff2,  g_ff2);
    cudaGetSymbolAddress((void**)&wqkv, g_wqkv);
    cudaGetSymbolAddress((void**)&wff,  g_wff);
    cudaGetSymbolAddress((void**)&wo,   g_wo);

    cudaFuncSetAttribute(attn_mma_kernel,
                         cudaFuncAttributeMaxDynamicSharedMemorySize, ATTN_SMEM_BYTES);

    // prepass: tf32-round all weights (read 32x per layer afterwards)
    round_copy_kernel<<<592, 256>>>(Wqkv, wqkv, NLAY * DMOD * 3 * DMOD / 4);
    round_copy_kernel<<<592, 256>>>(Wff,  wff,  NLAY * DMOD * DFFV / 4);
    round_copy_kernel<<<592, 256>>>(Wo,   wo,   NLAY * DFFV * DMOD / 4);

    embed_kernel<<<ROWS, 128>>>(x, emb);

    for (int l = 0; l < NLAY; ++l) {
        // QKV projection: A = g_htf (pre-rounded), B = pre-rounded weights
        gemm_tf32<0><<<dim3(1536 / 128, ROWS / 128), 256>>>(
            htf, wqkv + (size_t)l * DMOD * 3 * DMOD, bqkv + (size_t)l * 3 * DMOD,
            qkv, ROWS, 3 * DMOD, DMOD);

        split_qkv_kernel<<<ROWS, 384>>>();

        attn_mma_kernel<<<dim3(TT / 64, NH), 128, ATTN_SMEM_BYTES>>>();

        add_ln_kernel<true><<<ROWS, 256>>>(h, att,
            g1 + (size_t)l * DMOD, beta1 + (size_t)l * DMOD, h);

        // FF1: output relu'd + tf32-rounded (feeds FF2's A directly)
        gemm_tf32<1><<<dim3(DFFV / 128, ROWS / 128), 256>>>(
            htf, wff + (size_t)l * DMOD * DFFV, bff + (size_t)l * DFFV,
            ff1, ROWS, DFFV, DMOD);

        gemm_tf32<0><<<dim3(DMOD / 128, ROWS / 128), 256>>>(
            ff1, wo + (size_t)l * DFFV * DMOD, bo + (size_t)l * DMOD,
            ff2, ROWS, DMOD, DFFV);

        if (l == NLAY - 1)
            add_ln_kernel<false><<<ROWS, 256>>>(h, ff2,
                g2 + (size_t)l * DMOD, beta2 + (size_t)l * DMOD, out);
        else
            add_ln_kernel<true><<<ROWS, 256>>>(h, ff2,
                g2 + (size_t)l * DMOD, beta2 + (size_t)l * DMOD, h);
    }
}